// round 2
// baseline (speedup 1.0000x reference)
#include <cuda_runtime.h>

#define EMBED   1024
#define NHEADS  16
#define HDIM    64
#define BATCH   2
#define SEQ     2048
#define MROWS   (BATCH*SEQ)   // 4096

#define NEG_INF (-1e30f)

// Scratch (device globals — no allocation allowed)
__device__ float g_Q[(size_t)BATCH*NHEADS*SEQ*HDIM];
__device__ float g_K[(size_t)BATCH*NHEADS*SEQ*HDIM];
__device__ float g_V[(size_t)BATCH*NHEADS*SEQ*HDIM];
__device__ float g_ctx[(size_t)BATCH*SEQ*EMBED];

// ---------------------------------------------------------------------------
// SGEMM: out[row][col] = sum_k A[row][k] * Bw[col][k] + bias[col]
// A: [M,K] row-major, Bw: [N,K] row-major (i.e. computes A @ Bw^T + bias).
// MODE 0: A = x input, scatter result into g_Q/g_K/g_V ([B,H,S,D] layout)
// MODE 1: A = g_ctx,   write result to C
// Tile: 128x128, K-step 8, 256 threads, 8x8 per thread.
// ---------------------------------------------------------------------------
template<int MODE>
__global__ __launch_bounds__(256, 2)
void sgemm_kernel(const float* __restrict__ A, const float* __restrict__ Bw,
                  const float* __restrict__ bias, float* __restrict__ C,
                  int M, int N, int K)
{
    __shared__ float As[8][128];
    __shared__ float Bs[8][128];

    const int tid = threadIdx.x;
    const int tx = tid & 15;       // col group 0..15
    const int ty = tid >> 4;       // row group 0..15
    const int bm = blockIdx.y * 128;
    const int bn = blockIdx.x * 128;

    const int lr = tid >> 1;           // 0..127 tile row for loading
    const int lk = (tid & 1) * 4;      // k sub-offset 0 or 4

    const float* Abase = (MODE == 1) ? (const float*)g_ctx : A;
    const float* Ap = Abase + (size_t)(bm + lr) * K + lk;
    const float* Bp = Bw    + (size_t)(bn + lr) * K + lk;

    float acc[8][8];
    #pragma unroll
    for (int i = 0; i < 8; i++)
        #pragma unroll
        for (int j = 0; j < 8; j++) acc[i][j] = 0.f;

    for (int k0 = 0; k0 < K; k0 += 8) {
        float4 a4 = *(const float4*)(Ap + k0);
        float4 b4 = *(const float4*)(Bp + k0);
        __syncthreads();
        As[lk+0][lr] = a4.x; As[lk+1][lr] = a4.y;
        As[lk+2][lr] = a4.z; As[lk+3][lr] = a4.w;
        Bs[lk+0][lr] = b4.x; Bs[lk+1][lr] = b4.y;
        Bs[lk+2][lr] = b4.z; Bs[lk+3][lr] = b4.w;
        __syncthreads();

        #pragma unroll
        for (int kk = 0; kk < 8; kk++) {
            float ra[8], rb[8];
            *(float4*)(ra)     = *(const float4*)&As[kk][ty*8];
            *(float4*)(ra + 4) = *(const float4*)&As[kk][ty*8 + 4];
            *(float4*)(rb)     = *(const float4*)&Bs[kk][tx*8];
            *(float4*)(rb + 4) = *(const float4*)&Bs[kk][tx*8 + 4];
            #pragma unroll
            for (int i = 0; i < 8; i++)
                #pragma unroll
                for (int j = 0; j < 8; j++)
                    acc[i][j] = fmaf(ra[i], rb[j], acc[i][j]);
        }
    }

    #pragma unroll
    for (int i = 0; i < 8; i++) {
        const int row = bm + ty*8 + i;
        #pragma unroll
        for (int j = 0; j < 8; j++) {
            const int col = bn + tx*8 + j;
            const float v = acc[i][j] + bias[col];
            if (MODE == 0) {
                const int bb  = row / SEQ;
                const int ss  = row % SEQ;
                const int sel = col / EMBED;
                const int e   = col % EMBED;
                const int hh  = e / HDIM;
                const int dd  = e % HDIM;
                const size_t idx = ((size_t)(bb*NHEADS + hh)*SEQ + ss)*HDIM + dd;
                if (sel == 0)      g_Q[idx] = v;
                else if (sel == 1) g_K[idx] = v;
                else               g_V[idx] = v;
            } else {
                C[(size_t)row * N + col] = v;
            }
        }
    }
}

// ---------------------------------------------------------------------------
// Flash attention (causal), fp32.
// Grid: (SEQ/64 q-tiles, B*H). Block: 256 threads (16x16), 4x4 micro-tiles.
// smem: Qs[d][r], Ks[d][c] (transposed, broadcast-friendly), Vs[c][d],
//       Ps[c][r] padded to 65 for conflict avoidance.
// ---------------------------------------------------------------------------
#define ATTN_SMEM_FLOATS (3*64*64 + 64*65)
#define ATTN_SMEM_BYTES  (ATTN_SMEM_FLOATS * 4)

__global__ __launch_bounds__(256)
void attn_kernel()
{
    extern __shared__ float sm[];
    float (*Qs)[64] = (float(*)[64])(sm);              // [d][r]
    float (*Ks)[64] = (float(*)[64])(sm + 64*64);      // [d][c]
    float (*Vs)[64] = (float(*)[64])(sm + 2*64*64);    // [c][d]
    float (*Ps)[65] = (float(*)[65])(sm + 3*64*64);    // [c][r] padded

    const int qt = blockIdx.x;          // q tile 0..31
    const int bh = blockIdx.y;          // 0..31
    const int bb = bh / NHEADS;
    const int hh = bh % NHEADS;

    const float* Qg = g_Q + (size_t)bh * SEQ * HDIM;
    const float* Kg = g_K + (size_t)bh * SEQ * HDIM;
    const float* Vg = g_V + (size_t)bh * SEQ * HDIM;

    const int tid = threadIdx.x;
    const int tx = tid & 15;
    const int ty = tid >> 4;
    const int qbase = qt * 64;

    // Load Q tile transposed: Qs[d][r]
    {
        const int r  = tid >> 2;          // 0..63
        const int d0 = (tid & 3) * 16;    // 0,16,32,48
        #pragma unroll
        for (int u = 0; u < 4; u++) {
            float4 q4 = *(const float4*)(Qg + (size_t)(qbase + r)*HDIM + d0 + u*4);
            Qs[d0+u*4+0][r] = q4.x;
            Qs[d0+u*4+1][r] = q4.y;
            Qs[d0+u*4+2][r] = q4.z;
            Qs[d0+u*4+3][r] = q4.w;
        }
    }

    float acc[4][4];
    float mrow[4], lrow[4];
    #pragma unroll
    for (int i = 0; i < 4; i++) {
        mrow[i] = NEG_INF; lrow[i] = 0.f;
        #pragma unroll
        for (int j = 0; j < 4; j++) acc[i][j] = 0.f;
    }

    for (int kt = 0; kt <= qt; kt++) {
        const int kbase = kt * 64;
        __syncthreads();   // previous iteration's PV / P reads done

        // Load K tile (transposed) and V tile (natural)
        {
            const int r  = tid >> 2;
            const int d0 = (tid & 3) * 16;
            #pragma unroll
            for (int u = 0; u < 4; u++) {
                float4 k4 = *(const float4*)(Kg + (size_t)(kbase + r)*HDIM + d0 + u*4);
                Ks[d0+u*4+0][r] = k4.x;
                Ks[d0+u*4+1][r] = k4.y;
                Ks[d0+u*4+2][r] = k4.z;
                Ks[d0+u*4+3][r] = k4.w;
                float4 v4 = *(const float4*)(Vg + (size_t)(kbase + r)*HDIM + d0 + u*4);
                *(float4*)&Vs[r][d0+u*4] = v4;
            }
        }
        __syncthreads();

        // Scores: s[i][j] = sum_d Q[qr][d] * K[kc][d]
        float s[4][4];
        #pragma unroll
        for (int i = 0; i < 4; i++)
            #pragma unroll
            for (int j = 0; j < 4; j++) s[i][j] = 0.f;

        #pragma unroll 8
        for (int d = 0; d < 64; d++) {
            float4 qv = *(const float4*)&Qs[d][ty*4];   // broadcast in half-warp
            float4 kv = *(const float4*)&Ks[d][tx*4];   // conflict-free
            float qa[4] = {qv.x, qv.y, qv.z, qv.w};
            float ka[4] = {kv.x, kv.y, kv.z, kv.w};
            #pragma unroll
            for (int i = 0; i < 4; i++)
                #pragma unroll
                for (int j = 0; j < 4; j++)
                    s[i][j] = fmaf(qa[i], ka[j], s[i][j]);
        }

        const bool diag = (kt == qt);
        #pragma unroll
        for (int i = 0; i < 4; i++) {
            const int qi = qbase + ty*4 + i;
            float mx = NEG_INF;
            #pragma unroll
            for (int j = 0; j < 4; j++) {
                float sv = s[i][j] * 0.125f;   // 1/sqrt(64)
                if (diag && (kbase + tx*4 + j > qi)) sv = NEG_INF;
                s[i][j] = sv;
                mx = fmaxf(mx, sv);
            }
            // row-max across the 16 threads sharing this row group (width-16 shfl)
            #pragma unroll
            for (int off = 8; off >= 1; off >>= 1)
                mx = fmaxf(mx, __shfl_xor_sync(0xffffffffu, mx, off, 16));

            const float newm = fmaxf(mrow[i], mx);
            const float fac  = __expf(mrow[i] - newm);
            float psum = 0.f;
            #pragma unroll
            for (int j = 0; j < 4; j++) {
                float p = __expf(s[i][j] - newm);
                s[i][j] = p;
                psum += p;
            }
            #pragma unroll
            for (int off = 8; off >= 1; off >>= 1)
                psum += __shfl_xor_sync(0xffffffffu, psum, off, 16);

            lrow[i] = lrow[i] * fac + psum;
            mrow[i] = newm;
            #pragma unroll
            for (int j = 0; j < 4; j++) acc[i][j] *= fac;
        }

        // Write P transposed: Ps[c][r]
        #pragma unroll
        for (int j = 0; j < 4; j++)
            #pragma unroll
            for (int i = 0; i < 4; i++)
                Ps[tx*4 + j][ty*4 + i] = s[i][j];
        __syncthreads();

        // PV: acc[i][j] += P[qr][c] * V[c][dj]
        #pragma unroll 8
        for (int c = 0; c < 64; c++) {
            float pa[4];
            #pragma unroll
            for (int i = 0; i < 4; i++) pa[i] = Ps[c][ty*4 + i];  // broadcast
            float4 vv = *(const float4*)&Vs[c][tx*4];             // conflict-free
            float va[4] = {vv.x, vv.y, vv.z, vv.w};
            #pragma unroll
            for (int i = 0; i < 4; i++)
                #pragma unroll
                for (int j = 0; j < 4; j++)
                    acc[i][j] = fmaf(pa[i], va[j], acc[i][j]);
        }
    }

    // Finalize: divide by l and write ctx[b][s][h*64+d]
    #pragma unroll
    for (int i = 0; i < 4; i++) {
        const float inv = 1.f / lrow[i];
        const int srow = qbase + ty*4 + i;
        float* dst = g_ctx + ((size_t)bb*SEQ + srow)*EMBED + hh*HDIM + tx*4;
        float4 o;
        o.x = acc[i][0] * inv;
        o.y = acc[i][1] * inv;
        o.z = acc[i][2] * inv;
        o.w = acc[i][3] * inv;
        *(float4*)dst = o;
    }
}

// ---------------------------------------------------------------------------
extern "C" void kernel_launch(void* const* d_in, const int* in_sizes, int n_in,
                              void* d_out, int out_size)
{
    const float* x     = (const float*)d_in[0];   // [B,S,E]
    const float* w_qkv = (const float*)d_in[1];   // [3E,E]
    const float* b_qkv = (const float*)d_in[2];   // [3E]
    const float* w_out = (const float*)d_in[3];   // [E,E]
    const float* b_out = (const float*)d_in[4];   // [E]
    float* out = (float*)d_out;                   // [B,S,E]

    cudaFuncSetAttribute(attn_kernel,
                         cudaFuncAttributeMaxDynamicSharedMemorySize,
                         ATTN_SMEM_BYTES);

    dim3 blk(256);

    // 1. QKV projection + head split: x @ w_qkv^T + b_qkv -> g_Q/g_K/g_V
    sgemm_kernel<0><<<dim3((3*EMBED)/128, MROWS/128), blk>>>(
        x, w_qkv, b_qkv, nullptr, MROWS, 3*EMBED, EMBED);

    // 2. Causal flash attention -> g_ctx
    attn_kernel<<<dim3(SEQ/64, BATCH*NHEADS), blk, ATTN_SMEM_BYTES>>>();

    // 3. Output projection: g_ctx @ w_out^T + b_out -> out
    sgemm_kernel<1><<<dim3(EMBED/128, MROWS/128), blk>>>(
        nullptr, w_out, b_out, out, MROWS, EMBED, EMBED);
}

// round 3
// speedup vs baseline: 1.4039x; 1.4039x over previous
#include <cuda_runtime.h>
#include <cuda_bf16.h>
#include <cstdint>

#define EMBED   1024
#define NHEADS  16
#define HDIM    64
#define BATCH   2
#define SEQ     2048
#define MROWS   (BATCH*SEQ)   // 4096

#define NEG_INF (-1e30f)

// Scratch (device globals — no allocation allowed)
__device__ float g_Q[(size_t)BATCH*NHEADS*SEQ*HDIM];
__device__ float g_K[(size_t)BATCH*NHEADS*SEQ*HDIM];
__device__ float g_V[(size_t)BATCH*NHEADS*SEQ*HDIM];
__device__ float g_ctx[(size_t)BATCH*SEQ*EMBED];

// ---------------------------------------------------------------------------
// PTX helpers
// ---------------------------------------------------------------------------
__device__ __forceinline__ uint32_t saddr(const void* p) {
    return (uint32_t)__cvta_generic_to_shared(p);
}

__device__ __forceinline__ void ldsm_x4(uint32_t& r0, uint32_t& r1,
                                        uint32_t& r2, uint32_t& r3, uint32_t a) {
    asm volatile("ldmatrix.sync.aligned.m8n8.x4.shared.b16 {%0,%1,%2,%3}, [%4];"
                 : "=r"(r0), "=r"(r1), "=r"(r2), "=r"(r3) : "r"(a));
}

__device__ __forceinline__ void mma_bf16(float* c, const uint32_t* a, const uint32_t* b) {
    asm volatile(
        "mma.sync.aligned.m16n8k16.row.col.f32.bf16.bf16.f32 "
        "{%0,%1,%2,%3}, {%4,%5,%6,%7}, {%8,%9}, {%0,%1,%2,%3};"
        : "+f"(c[0]), "+f"(c[1]), "+f"(c[2]), "+f"(c[3])
        : "r"(a[0]), "r"(a[1]), "r"(a[2]), "r"(a[3]), "r"(b[0]), "r"(b[1]));
}

__device__ __forceinline__ uint32_t pk(__nv_bfloat16 a, __nv_bfloat16 b) {
    return (uint32_t)__bfloat16_as_ushort(a) | ((uint32_t)__bfloat16_as_ushort(b) << 16);
}

// split fp32 -> bf16 hi + bf16 lo, store 4 values (8B) to each smem array
__device__ __forceinline__ void cvt_store(float4 f, __nv_bfloat16* hp, __nv_bfloat16* lp) {
    float ff[4] = {f.x, f.y, f.z, f.w};
    __nv_bfloat16 h[4], l[4];
    #pragma unroll
    for (int i = 0; i < 4; i++) {
        h[i] = __float2bfloat16(ff[i]);
        l[i] = __float2bfloat16(ff[i] - __bfloat162float(h[i]));
    }
    uint2 hv, lv;
    hv.x = pk(h[0], h[1]); hv.y = pk(h[2], h[3]);
    lv.x = pk(l[0], l[1]); lv.y = pk(l[2], l[3]);
    *(uint2*)hp = hv;
    *(uint2*)lp = lv;
}

__device__ __forceinline__ void scatter_qkv(int row, int col, float v0, float v1) {
    const int sel = col >> 10;        // 0=Q 1=K 2=V
    const int e   = col & 1023;
    const int hh  = e >> 6;
    const int dd  = e & 63;
    const int bb  = row >> 11;
    const int ss  = row & 2047;
    float* p = (sel == 0) ? g_Q : (sel == 1) ? g_K : g_V;
    float2 v; v.x = v0; v.y = v1;
    *(float2*)&p[(((size_t)(bb*NHEADS + hh))*SEQ + ss)*HDIM + dd] = v;
}

// ---------------------------------------------------------------------------
// Tensor-core GEMM (split-bf16, ~fp32 accuracy): out = A @ Bw^T + bias
// A: [M,K] row-major fp32, Bw: [N,K] row-major fp32.
// MODE 0: A = x, scatter into g_Q/g_K/g_V.  MODE 1: A = g_ctx, write C.
// CTA tile 128x128, K-step 32, 8 warps (2m x 4n), warp tile 64x32.
// smem rows padded to 40 bf16 (80B) -> conflict-free ldmatrix.
// ---------------------------------------------------------------------------
template<int MODE>
__global__ __launch_bounds__(256, 1)
void gemm_tc(const float* __restrict__ A, const float* __restrict__ Bw,
             const float* __restrict__ bias, float* __restrict__ C,
             int M, int N, int K)
{
    __shared__ __nv_bfloat16 Ah[128][40];
    __shared__ __nv_bfloat16 Al[128][40];
    __shared__ __nv_bfloat16 Bh[128][40];
    __shared__ __nv_bfloat16 Bl[128][40];

    const int tid  = threadIdx.x;
    const int lane = tid & 31;
    const int warp = tid >> 5;
    const int wm   = warp >> 2;   // 0..1
    const int wn   = warp & 3;    // 0..3
    const int bm   = blockIdx.y * 128;
    const int bn   = blockIdx.x * 128;

    const float* Abase = (MODE == 1) ? (const float*)g_ctx : A;

    // global loader: each thread owns one (row, 16-float half-row) of the 128x32 tile
    const int lr  = tid >> 1;            // 0..127
    const int lc0 = (tid & 1) * 16;      // 0 or 16
    const float* Ap = Abase + (size_t)(bm + lr) * K + lc0;
    const float* Bp = Bw    + (size_t)(bn + lr) * K + lc0;

    float acc[16][4];
    #pragma unroll
    for (int i = 0; i < 16; i++)
        #pragma unroll
        for (int j = 0; j < 4; j++) acc[i][j] = 0.f;

    // ldmatrix source coordinates
    const int arow = wm*64 + (lane & 15);
    const int acol = ((lane >> 4) & 1) * 8;
    const int brow = wn*32 + (lane & 7) + ((lane >> 4) & 1) * 8;
    const int bcol = ((lane >> 3) & 1) * 8;

    float4 pa[4], pb[4];
    #pragma unroll
    for (int u = 0; u < 4; u++) {
        pa[u] = *(const float4*)(Ap + u*4);
        pb[u] = *(const float4*)(Bp + u*4);
    }

    for (int k0 = 0; k0 < K; k0 += 32) {
        // commit prefetched tile to smem (split to hi/lo bf16)
        #pragma unroll
        for (int u = 0; u < 4; u++) {
            cvt_store(pa[u], &Ah[lr][lc0 + u*4], &Al[lr][lc0 + u*4]);
            cvt_store(pb[u], &Bh[lr][lc0 + u*4], &Bl[lr][lc0 + u*4]);
        }
        __syncthreads();

        // prefetch next k-step (overlaps with mma work below)
        if (k0 + 32 < K) {
            #pragma unroll
            for (int u = 0; u < 4; u++) {
                pa[u] = *(const float4*)(Ap + (k0 + 32) + u*4);
                pb[u] = *(const float4*)(Bp + (k0 + 32) + u*4);
            }
        }

        #pragma unroll
        for (int kk = 0; kk < 2; kk++) {
            uint32_t ah[4][4], al[4][4], bh[2][4], bl[2][4];
            #pragma unroll
            for (int t = 0; t < 4; t++) {
                ldsm_x4(ah[t][0], ah[t][1], ah[t][2], ah[t][3],
                        saddr(&Ah[arow + t*16][kk*16 + acol]));
                ldsm_x4(al[t][0], al[t][1], al[t][2], al[t][3],
                        saddr(&Al[arow + t*16][kk*16 + acol]));
            }
            #pragma unroll
            for (int p = 0; p < 2; p++) {
                ldsm_x4(bh[p][0], bh[p][1], bh[p][2], bh[p][3],
                        saddr(&Bh[p*16 + brow][kk*16 + bcol]));
                ldsm_x4(bl[p][0], bl[p][1], bl[p][2], bl[p][3],
                        saddr(&Bl[p*16 + brow][kk*16 + bcol]));
            }
            #pragma unroll
            for (int t = 0; t < 4; t++) {
                #pragma unroll
                for (int n = 0; n < 4; n++) {
                    float* c = acc[t*4 + n];
                    const uint32_t* Bhf = &bh[n >> 1][(n & 1) * 2];
                    const uint32_t* Blf = &bl[n >> 1][(n & 1) * 2];
                    mma_bf16(c, ah[t], Bhf);   // hi*hi
                    mma_bf16(c, ah[t], Blf);   // hi*lo
                    mma_bf16(c, al[t], Bhf);   // lo*hi
                }
            }
        }
        __syncthreads();
    }

    // epilogue
    #pragma unroll
    for (int t = 0; t < 4; t++) {
        const int r0 = bm + wm*64 + t*16 + (lane >> 2);
        #pragma unroll
        for (int n = 0; n < 4; n++) {
            const int col = bn + wn*32 + n*8 + (lane & 3)*2;
            const float b0 = bias[col], b1 = bias[col + 1];
            const float* c = acc[t*4 + n];
            if (MODE == 0) {
                scatter_qkv(r0,     col, c[0] + b0, c[1] + b1);
                scatter_qkv(r0 + 8, col, c[2] + b0, c[3] + b1);
            } else {
                float2 v0h; v0h.x = c[0] + b0; v0h.y = c[1] + b1;
                float2 v1h; v1h.x = c[2] + b0; v1h.y = c[3] + b1;
                *(float2*)&C[(size_t)r0       * N + col] = v0h;
                *(float2*)&C[(size_t)(r0 + 8) * N + col] = v1h;
            }
        }
    }
}

// ---------------------------------------------------------------------------
// Flash attention (causal), fp32. (unchanged this round)
// ---------------------------------------------------------------------------
#define ATTN_SMEM_FLOATS (3*64*64 + 64*65)
#define ATTN_SMEM_BYTES  (ATTN_SMEM_FLOATS * 4)

__global__ __launch_bounds__(256)
void attn_kernel()
{
    extern __shared__ float sm[];
    float (*Qs)[64] = (float(*)[64])(sm);              // [d][r]
    float (*Ks)[64] = (float(*)[64])(sm + 64*64);      // [d][c]
    float (*Vs)[64] = (float(*)[64])(sm + 2*64*64);    // [c][d]
    float (*Ps)[65] = (float(*)[65])(sm + 3*64*64);    // [c][r] padded

    const int qt = blockIdx.x;
    const int bh = blockIdx.y;
    const int bb = bh / NHEADS;
    const int hh = bh % NHEADS;

    const float* Qg = g_Q + (size_t)bh * SEQ * HDIM;
    const float* Kg = g_K + (size_t)bh * SEQ * HDIM;
    const float* Vg = g_V + (size_t)bh * SEQ * HDIM;

    const int tid = threadIdx.x;
    const int tx = tid & 15;
    const int ty = tid >> 4;
    const int qbase = qt * 64;

    {
        const int r  = tid >> 2;
        const int d0 = (tid & 3) * 16;
        #pragma unroll
        for (int u = 0; u < 4; u++) {
            float4 q4 = *(const float4*)(Qg + (size_t)(qbase + r)*HDIM + d0 + u*4);
            Qs[d0+u*4+0][r] = q4.x;
            Qs[d0+u*4+1][r] = q4.y;
            Qs[d0+u*4+2][r] = q4.z;
            Qs[d0+u*4+3][r] = q4.w;
        }
    }

    float acc[4][4];
    float mrow[4], lrow[4];
    #pragma unroll
    for (int i = 0; i < 4; i++) {
        mrow[i] = NEG_INF; lrow[i] = 0.f;
        #pragma unroll
        for (int j = 0; j < 4; j++) acc[i][j] = 0.f;
    }

    for (int kt = 0; kt <= qt; kt++) {
        const int kbase = kt * 64;
        __syncthreads();

        {
            const int r  = tid >> 2;
            const int d0 = (tid & 3) * 16;
            #pragma unroll
            for (int u = 0; u < 4; u++) {
                float4 k4 = *(const float4*)(Kg + (size_t)(kbase + r)*HDIM + d0 + u*4);
                Ks[d0+u*4+0][r] = k4.x;
                Ks[d0+u*4+1][r] = k4.y;
                Ks[d0+u*4+2][r] = k4.z;
                Ks[d0+u*4+3][r] = k4.w;
                float4 v4 = *(const float4*)(Vg + (size_t)(kbase + r)*HDIM + d0 + u*4);
                *(float4*)&Vs[r][d0+u*4] = v4;
            }
        }
        __syncthreads();

        float s[4][4];
        #pragma unroll
        for (int i = 0; i < 4; i++)
            #pragma unroll
            for (int j = 0; j < 4; j++) s[i][j] = 0.f;

        #pragma unroll 8
        for (int d = 0; d < 64; d++) {
            float4 qv = *(const float4*)&Qs[d][ty*4];
            float4 kv = *(const float4*)&Ks[d][tx*4];
            float qa[4] = {qv.x, qv.y, qv.z, qv.w};
            float ka[4] = {kv.x, kv.y, kv.z, kv.w};
            #pragma unroll
            for (int i = 0; i < 4; i++)
                #pragma unroll
                for (int j = 0; j < 4; j++)
                    s[i][j] = fmaf(qa[i], ka[j], s[i][j]);
        }

        const bool diag = (kt == qt);
        #pragma unroll
        for (int i = 0; i < 4; i++) {
            const int qi = qbase + ty*4 + i;
            float mx = NEG_INF;
            #pragma unroll
            for (int j = 0; j < 4; j++) {
                float sv = s[i][j] * 0.125f;
                if (diag && (kbase + tx*4 + j > qi)) sv = NEG_INF;
                s[i][j] = sv;
                mx = fmaxf(mx, sv);
            }
            #pragma unroll
            for (int off = 8; off >= 1; off >>= 1)
                mx = fmaxf(mx, __shfl_xor_sync(0xffffffffu, mx, off, 16));

            const float newm = fmaxf(mrow[i], mx);
            const float fac  = __expf(mrow[i] - newm);
            float psum = 0.f;
            #pragma unroll
            for (int j = 0; j < 4; j++) {
                float p = __expf(s[i][j] - newm);
                s[i][j] = p;
                psum += p;
            }
            #pragma unroll
            for (int off = 8; off >= 1; off >>= 1)
                psum += __shfl_xor_sync(0xffffffffu, psum, off, 16);

            lrow[i] = lrow[i] * fac + psum;
            mrow[i] = newm;
            #pragma unroll
            for (int j = 0; j < 4; j++) acc[i][j] *= fac;
        }

        #pragma unroll
        for (int j = 0; j < 4; j++)
            #pragma unroll
            for (int i = 0; i < 4; i++)
                Ps[tx*4 + j][ty*4 + i] = s[i][j];
        __syncthreads();

        #pragma unroll 8
        for (int c = 0; c < 64; c++) {
            float pa[4];
            #pragma unroll
            for (int i = 0; i < 4; i++) pa[i] = Ps[c][ty*4 + i];
            float4 vv = *(const float4*)&Vs[c][tx*4];
            float va[4] = {vv.x, vv.y, vv.z, vv.w};
            #pragma unroll
            for (int i = 0; i < 4; i++)
                #pragma unroll
                for (int j = 0; j < 4; j++)
                    acc[i][j] = fmaf(pa[i], va[j], acc[i][j]);
        }
    }

    #pragma unroll
    for (int i = 0; i < 4; i++) {
        const float inv = 1.f / lrow[i];
        const int srow = qbase + ty*4 + i;
        float* dst = g_ctx + ((size_t)bb*SEQ + srow)*EMBED + hh*HDIM + tx*4;
        float4 o;
        o.x = acc[i][0] * inv;
        o.y = acc[i][1] * inv;
        o.z = acc[i][2] * inv;
        o.w = acc[i][3] * inv;
        *(float4*)dst = o;
    }
}

// ---------------------------------------------------------------------------
extern "C" void kernel_launch(void* const* d_in, const int* in_sizes, int n_in,
                              void* d_out, int out_size)
{
    const float* x     = (const float*)d_in[0];   // [B,S,E]
    const float* w_qkv = (const float*)d_in[1];   // [3E,E]
    const float* b_qkv = (const float*)d_in[2];   // [3E]
    const float* w_out = (const float*)d_in[3];   // [E,E]
    const float* b_out = (const float*)d_in[4];   // [E]
    float* out = (float*)d_out;                   // [B,S,E]

    cudaFuncSetAttribute(attn_kernel,
                         cudaFuncAttributeMaxDynamicSharedMemorySize,
                         ATTN_SMEM_BYTES);

    dim3 blk(256);

    // 1. QKV projection + head split (tensor cores, split-bf16)
    gemm_tc<0><<<dim3((3*EMBED)/128, MROWS/128), blk>>>(
        x, w_qkv, b_qkv, nullptr, MROWS, 3*EMBED, EMBED);

    // 2. Causal flash attention -> g_ctx
    attn_kernel<<<dim3(SEQ/64, BATCH*NHEADS), blk, ATTN_SMEM_BYTES>>>();

    // 3. Output projection (tensor cores, split-bf16)
    gemm_tc<1><<<dim3(EMBED/128, MROWS/128), blk>>>(
        nullptr, w_out, b_out, out, MROWS, EMBED, EMBED);
}

// round 4
// speedup vs baseline: 2.3162x; 1.6498x over previous
#include <cuda_runtime.h>
#include <cuda_bf16.h>
#include <cstdint>

#define EMBED   1024
#define NHEADS  16
#define HDIM    64
#define BATCH   2
#define SEQ     2048
#define MROWS   (BATCH*SEQ)   // 4096

#define NEG_INF (-1e30f)

// Scratch (device globals — no allocation allowed)
__device__ float g_Q[(size_t)BATCH*NHEADS*SEQ*HDIM];
__device__ float g_K[(size_t)BATCH*NHEADS*SEQ*HDIM];
__device__ float g_V[(size_t)BATCH*NHEADS*SEQ*HDIM];
__device__ float g_ctx[(size_t)BATCH*SEQ*EMBED];

// ---------------------------------------------------------------------------
// PTX helpers
// ---------------------------------------------------------------------------
__device__ __forceinline__ uint32_t saddr(const void* p) {
    return (uint32_t)__cvta_generic_to_shared(p);
}

__device__ __forceinline__ void ldsm_x4(uint32_t& r0, uint32_t& r1,
                                        uint32_t& r2, uint32_t& r3, uint32_t a) {
    asm volatile("ldmatrix.sync.aligned.m8n8.x4.shared.b16 {%0,%1,%2,%3}, [%4];"
                 : "=r"(r0), "=r"(r1), "=r"(r2), "=r"(r3) : "r"(a));
}

__device__ __forceinline__ void ldsm_x4_t(uint32_t& r0, uint32_t& r1,
                                          uint32_t& r2, uint32_t& r3, uint32_t a) {
    asm volatile("ldmatrix.sync.aligned.m8n8.x4.trans.shared.b16 {%0,%1,%2,%3}, [%4];"
                 : "=r"(r0), "=r"(r1), "=r"(r2), "=r"(r3) : "r"(a));
}

__device__ __forceinline__ void mma_bf16(float* c, const uint32_t* a, const uint32_t* b) {
    asm volatile(
        "mma.sync.aligned.m16n8k16.row.col.f32.bf16.bf16.f32 "
        "{%0,%1,%2,%3}, {%4,%5,%6,%7}, {%8,%9}, {%0,%1,%2,%3};"
        : "+f"(c[0]), "+f"(c[1]), "+f"(c[2]), "+f"(c[3])
        : "r"(a[0]), "r"(a[1]), "r"(a[2]), "r"(a[3]), "r"(b[0]), "r"(b[1]));
}

__device__ __forceinline__ uint32_t pk(__nv_bfloat16 a, __nv_bfloat16 b) {
    return (uint32_t)__bfloat16_as_ushort(a) | ((uint32_t)__bfloat16_as_ushort(b) << 16);
}

// split fp32 -> bf16 hi + bf16 lo, store 4 values (8B) to each smem array
__device__ __forceinline__ void cvt_store(float4 f, __nv_bfloat16* hp, __nv_bfloat16* lp) {
    float ff[4] = {f.x, f.y, f.z, f.w};
    __nv_bfloat16 h[4], l[4];
    #pragma unroll
    for (int i = 0; i < 4; i++) {
        h[i] = __float2bfloat16(ff[i]);
        l[i] = __float2bfloat16(ff[i] - __bfloat162float(h[i]));
    }
    uint2 hv, lv;
    hv.x = pk(h[0], h[1]); hv.y = pk(h[2], h[3]);
    lv.x = pk(l[0], l[1]); lv.y = pk(l[2], l[3]);
    *(uint2*)hp = hv;
    *(uint2*)lp = lv;
}

// split two floats into packed hi bf16x2 and lo bf16x2 (a -> low half)
__device__ __forceinline__ void split_pack(float a, float b, uint32_t& hi, uint32_t& lo) {
    __nv_bfloat16 ah = __float2bfloat16(a), bh = __float2bfloat16(b);
    hi = pk(ah, bh);
    float al = a - __bfloat162float(ah);
    float bl = b - __bfloat162float(bh);
    lo = pk(__float2bfloat16(al), __float2bfloat16(bl));
}

__device__ __forceinline__ void scatter_qkv(int row, int col, float v0, float v1) {
    const int sel = col >> 10;        // 0=Q 1=K 2=V
    const int e   = col & 1023;
    const int hh  = e >> 6;
    const int dd  = e & 63;
    const int bb  = row >> 11;
    const int ss  = row & 2047;
    float* p = (sel == 0) ? g_Q : (sel == 1) ? g_K : g_V;
    float2 v; v.x = v0; v.y = v1;
    *(float2*)&p[(((size_t)(bb*NHEADS + hh))*SEQ + ss)*HDIM + dd] = v;
}

// ---------------------------------------------------------------------------
// Tensor-core GEMM (split-bf16, ~fp32 accuracy): out = A @ Bw^T + bias
// (unchanged from round 2)
// ---------------------------------------------------------------------------
template<int MODE>
__global__ __launch_bounds__(256, 1)
void gemm_tc(const float* __restrict__ A, const float* __restrict__ Bw,
             const float* __restrict__ bias, float* __restrict__ C,
             int M, int N, int K)
{
    __shared__ __nv_bfloat16 Ah[128][40];
    __shared__ __nv_bfloat16 Al[128][40];
    __shared__ __nv_bfloat16 Bh[128][40];
    __shared__ __nv_bfloat16 Bl[128][40];

    const int tid  = threadIdx.x;
    const int lane = tid & 31;
    const int warp = tid >> 5;
    const int wm   = warp >> 2;
    const int wn   = warp & 3;
    const int bm   = blockIdx.y * 128;
    const int bn   = blockIdx.x * 128;

    const float* Abase = (MODE == 1) ? (const float*)g_ctx : A;

    const int lr  = tid >> 1;
    const int lc0 = (tid & 1) * 16;
    const float* Ap = Abase + (size_t)(bm + lr) * K + lc0;
    const float* Bp = Bw    + (size_t)(bn + lr) * K + lc0;

    float acc[16][4];
    #pragma unroll
    for (int i = 0; i < 16; i++)
        #pragma unroll
        for (int j = 0; j < 4; j++) acc[i][j] = 0.f;

    const int arow = wm*64 + (lane & 15);
    const int acol = ((lane >> 4) & 1) * 8;
    const int brow = wn*32 + (lane & 7) + ((lane >> 4) & 1) * 8;
    const int bcol = ((lane >> 3) & 1) * 8;

    float4 pa[4], pb[4];
    #pragma unroll
    for (int u = 0; u < 4; u++) {
        pa[u] = *(const float4*)(Ap + u*4);
        pb[u] = *(const float4*)(Bp + u*4);
    }

    for (int k0 = 0; k0 < K; k0 += 32) {
        #pragma unroll
        for (int u = 0; u < 4; u++) {
            cvt_store(pa[u], &Ah[lr][lc0 + u*4], &Al[lr][lc0 + u*4]);
            cvt_store(pb[u], &Bh[lr][lc0 + u*4], &Bl[lr][lc0 + u*4]);
        }
        __syncthreads();

        if (k0 + 32 < K) {
            #pragma unroll
            for (int u = 0; u < 4; u++) {
                pa[u] = *(const float4*)(Ap + (k0 + 32) + u*4);
                pb[u] = *(const float4*)(Bp + (k0 + 32) + u*4);
            }
        }

        #pragma unroll
        for (int kk = 0; kk < 2; kk++) {
            uint32_t ah[4][4], al[4][4], bh[2][4], bl[2][4];
            #pragma unroll
            for (int t = 0; t < 4; t++) {
                ldsm_x4(ah[t][0], ah[t][1], ah[t][2], ah[t][3],
                        saddr(&Ah[arow + t*16][kk*16 + acol]));
                ldsm_x4(al[t][0], al[t][1], al[t][2], al[t][3],
                        saddr(&Al[arow + t*16][kk*16 + acol]));
            }
            #pragma unroll
            for (int p = 0; p < 2; p++) {
                ldsm_x4(bh[p][0], bh[p][1], bh[p][2], bh[p][3],
                        saddr(&Bh[p*16 + brow][kk*16 + bcol]));
                ldsm_x4(bl[p][0], bl[p][1], bl[p][2], bl[p][3],
                        saddr(&Bl[p*16 + brow][kk*16 + bcol]));
            }
            #pragma unroll
            for (int t = 0; t < 4; t++) {
                #pragma unroll
                for (int n = 0; n < 4; n++) {
                    float* c = acc[t*4 + n];
                    const uint32_t* Bhf = &bh[n >> 1][(n & 1) * 2];
                    const uint32_t* Blf = &bl[n >> 1][(n & 1) * 2];
                    mma_bf16(c, ah[t], Bhf);
                    mma_bf16(c, ah[t], Blf);
                    mma_bf16(c, al[t], Bhf);
                }
            }
        }
        __syncthreads();
    }

    #pragma unroll
    for (int t = 0; t < 4; t++) {
        const int r0 = bm + wm*64 + t*16 + (lane >> 2);
        #pragma unroll
        for (int n = 0; n < 4; n++) {
            const int col = bn + wn*32 + n*8 + (lane & 3)*2;
            const float b0 = bias[col], b1 = bias[col + 1];
            const float* c = acc[t*4 + n];
            if (MODE == 0) {
                scatter_qkv(r0,     col, c[0] + b0, c[1] + b1);
                scatter_qkv(r0 + 8, col, c[2] + b0, c[3] + b1);
            } else {
                float2 v0h; v0h.x = c[0] + b0; v0h.y = c[1] + b1;
                float2 v1h; v1h.x = c[2] + b0; v1h.y = c[3] + b1;
                *(float2*)&C[(size_t)r0       * N + col] = v0h;
                *(float2*)&C[(size_t)(r0 + 8) * N + col] = v1h;
            }
        }
    }
}

// ---------------------------------------------------------------------------
// Tensor-core flash attention (causal), split-bf16 (~fp32 accuracy).
// q-tile 128, k-tile 64. 8 warps, each owns m16 rows of the q-tile.
// QK^T and P.V via mma.m16n8k16.bf16, 3 MMAs each (hi*hi + hi*lo + lo*hi).
// Q scaled by 1/sqrt(d) at load. S fragments re-packed in registers as A
// fragments for P.V. V fragments via ldmatrix.trans on natural [c][d] tiles.
// smem: Qh/Ql[128][72], Kh/Kl[64][72], Vh/Vl[64][72]  (72-pad: conflict-free)
// ---------------------------------------------------------------------------
#define ATTN_SMEM_BYTES (36864 * 2)   // 73728 B

__global__ __launch_bounds__(256, 1)
void attn_tc()
{
    typedef __nv_bfloat16 bf;
    extern __shared__ bf sb[];
    bf (*Qh)[72] = (bf(*)[72])(sb);
    bf (*Ql)[72] = (bf(*)[72])(sb + 9216);
    bf (*Kh)[72] = (bf(*)[72])(sb + 18432);
    bf (*Kl)[72] = (bf(*)[72])(sb + 23040);
    bf (*Vh)[72] = (bf(*)[72])(sb + 27648);
    bf (*Vl)[72] = (bf(*)[72])(sb + 32256);

    const int qt   = (int)(gridDim.x - 1) - (int)blockIdx.x;   // big tiles first
    const int bhid = blockIdx.y;
    const int bb   = bhid / NHEADS;
    const int hh   = bhid % NHEADS;

    const float* Qg = g_Q + (size_t)bhid * SEQ * HDIM;
    const float* Kg = g_K + (size_t)bhid * SEQ * HDIM;
    const float* Vg = g_V + (size_t)bhid * SEQ * HDIM;

    const int tid  = threadIdx.x;
    const int lane = tid & 31;
    const int w    = tid >> 5;
    const int qbase = qt * 128;

    // ---- load Q tile (scaled by 1/sqrt(64)), split hi/lo ----
    {
        const int lr = tid >> 1;            // 0..127
        const int c0 = (tid & 1) * 32;      // floats
        const float* src = Qg + (size_t)(qbase + lr) * HDIM + c0;
        #pragma unroll
        for (int u = 0; u < 8; u++) {
            float4 q4 = *(const float4*)(src + u*4);
            q4.x *= 0.125f; q4.y *= 0.125f; q4.z *= 0.125f; q4.w *= 0.125f;
            cvt_store(q4, &Qh[lr][c0 + u*4], &Ql[lr][c0 + u*4]);
        }
    }
    __syncthreads();

    // ---- Q fragments (held in registers for the whole kernel) ----
    uint32_t qfh[4][4], qfl[4][4];
    {
        const int arow = w*16 + (lane & 15);
        const int acol = ((lane >> 4) & 1) * 8;
        #pragma unroll
        for (int kc = 0; kc < 4; kc++) {
            ldsm_x4(qfh[kc][0], qfh[kc][1], qfh[kc][2], qfh[kc][3],
                    saddr(&Qh[arow][kc*16 + acol]));
            ldsm_x4(qfl[kc][0], qfl[kc][1], qfl[kc][2], qfl[kc][3],
                    saddr(&Ql[arow][kc*16 + acol]));
        }
    }

    float O[8][4];
    #pragma unroll
    for (int nt = 0; nt < 8; nt++)
        #pragma unroll
        for (int e = 0; e < 4; e++) O[nt][e] = 0.f;

    float m0 = NEG_INF, m1 = NEG_INF, l0 = 0.f, l1 = 0.f;
    const int r0g = qbase + w*16 + (lane >> 2);
    const int r1g = r0g + 8;
    const int wr  = qbase + w*16;

    // ldsm coords for K (non-trans, K[n][k]) and V (trans, V[k][n])
    const int krow = (lane & 7) + ((lane >> 4) & 1) * 8;
    const int kcol = ((lane >> 3) & 1) * 8;
    const int vrow = (lane & 7) + ((lane >> 3) & 1) * 8;
    const int vcol = ((lane >> 4) & 1) * 8;

    const int nktiles = 2*qt + 2;
    for (int kt = 0; kt < nktiles; kt++) {
        const int kbase = kt * 64;
        __syncthreads();   // all warps done reading K/V smem

        // ---- load K and V tiles, split hi/lo ----
        {
            const int kr = tid >> 2;            // 0..63
            const int c0 = (tid & 3) * 16;
            const float* ksrc = Kg + (size_t)(kbase + kr) * HDIM + c0;
            const float* vsrc = Vg + (size_t)(kbase + kr) * HDIM + c0;
            #pragma unroll
            for (int u = 0; u < 4; u++) {
                float4 k4 = *(const float4*)(ksrc + u*4);
                cvt_store(k4, &Kh[kr][c0 + u*4], &Kl[kr][c0 + u*4]);
                float4 v4 = *(const float4*)(vsrc + u*4);
                cvt_store(v4, &Vh[kr][c0 + u*4], &Vl[kr][c0 + u*4]);
            }
        }
        __syncthreads();

        if (wr + 15 < kbase) continue;   // this warp fully masked for this tile

        // ---- scores S = Q K^T ----
        float s[8][4];
        #pragma unroll
        for (int nt = 0; nt < 8; nt++)
            #pragma unroll
            for (int e = 0; e < 4; e++) s[nt][e] = 0.f;

        #pragma unroll
        for (int kc = 0; kc < 4; kc++) {
            uint32_t kh4[4][4], kl4[4][4];
            #pragma unroll
            for (int p = 0; p < 4; p++) {
                ldsm_x4(kh4[p][0], kh4[p][1], kh4[p][2], kh4[p][3],
                        saddr(&Kh[p*16 + krow][kc*16 + kcol]));
                ldsm_x4(kl4[p][0], kl4[p][1], kl4[p][2], kl4[p][3],
                        saddr(&Kl[p*16 + krow][kc*16 + kcol]));
            }
            #pragma unroll
            for (int nt = 0; nt < 8; nt++) {
                const uint32_t* Bhf = &kh4[nt >> 1][(nt & 1) * 2];
                const uint32_t* Blf = &kl4[nt >> 1][(nt & 1) * 2];
                mma_bf16(s[nt], qfh[kc], Bhf);
                mma_bf16(s[nt], qfh[kc], Blf);
                mma_bf16(s[nt], qfl[kc], Bhf);
            }
        }

        // ---- causal mask (only on diagonal-crossing tiles) ----
        if (kbase + 63 > wr) {
            #pragma unroll
            for (int nt = 0; nt < 8; nt++) {
                const int c0 = kbase + nt*8 + ((lane & 3) << 1);
                if (c0     > r0g) s[nt][0] = NEG_INF;
                if (c0 + 1 > r0g) s[nt][1] = NEG_INF;
                if (c0     > r1g) s[nt][2] = NEG_INF;
                if (c0 + 1 > r1g) s[nt][3] = NEG_INF;
            }
        }

        // ---- online softmax ----
        float mx0 = NEG_INF, mx1 = NEG_INF;
        #pragma unroll
        for (int nt = 0; nt < 8; nt++) {
            mx0 = fmaxf(mx0, fmaxf(s[nt][0], s[nt][1]));
            mx1 = fmaxf(mx1, fmaxf(s[nt][2], s[nt][3]));
        }
        mx0 = fmaxf(mx0, __shfl_xor_sync(0xffffffffu, mx0, 1));
        mx0 = fmaxf(mx0, __shfl_xor_sync(0xffffffffu, mx0, 2));
        mx1 = fmaxf(mx1, __shfl_xor_sync(0xffffffffu, mx1, 1));
        mx1 = fmaxf(mx1, __shfl_xor_sync(0xffffffffu, mx1, 2));

        const float nm0 = fmaxf(m0, mx0);
        const float nm1 = fmaxf(m1, mx1);
        const float f0 = __expf(m0 - nm0);
        const float f1 = __expf(m1 - nm1);

        float ps0 = 0.f, ps1 = 0.f;
        #pragma unroll
        for (int nt = 0; nt < 8; nt++) {
            s[nt][0] = __expf(s[nt][0] - nm0);
            s[nt][1] = __expf(s[nt][1] - nm0);
            s[nt][2] = __expf(s[nt][2] - nm1);
            s[nt][3] = __expf(s[nt][3] - nm1);
            ps0 += s[nt][0] + s[nt][1];
            ps1 += s[nt][2] + s[nt][3];
        }
        ps0 += __shfl_xor_sync(0xffffffffu, ps0, 1);
        ps0 += __shfl_xor_sync(0xffffffffu, ps0, 2);
        ps1 += __shfl_xor_sync(0xffffffffu, ps1, 1);
        ps1 += __shfl_xor_sync(0xffffffffu, ps1, 2);

        l0 = l0 * f0 + ps0;  m0 = nm0;
        l1 = l1 * f1 + ps1;  m1 = nm1;

        #pragma unroll
        for (int nt = 0; nt < 8; nt++) {
            O[nt][0] *= f0; O[nt][1] *= f0;
            O[nt][2] *= f1; O[nt][3] *= f1;
        }

        // ---- O += P V  (P from S fragments, split hi/lo) ----
        #pragma unroll
        for (int kc = 0; kc < 4; kc++) {
            uint32_t pah[4], pal[4];
            split_pack(s[2*kc  ][0], s[2*kc  ][1], pah[0], pal[0]);
            split_pack(s[2*kc  ][2], s[2*kc  ][3], pah[1], pal[1]);
            split_pack(s[2*kc+1][0], s[2*kc+1][1], pah[2], pal[2]);
            split_pack(s[2*kc+1][2], s[2*kc+1][3], pah[3], pal[3]);

            uint32_t vh4[4][4], vl4[4][4];
            #pragma unroll
            for (int p = 0; p < 4; p++) {
                ldsm_x4_t(vh4[p][0], vh4[p][1], vh4[p][2], vh4[p][3],
                          saddr(&Vh[kc*16 + vrow][p*16 + vcol]));
                ldsm_x4_t(vl4[p][0], vl4[p][1], vl4[p][2], vl4[p][3],
                          saddr(&Vl[kc*16 + vrow][p*16 + vcol]));
            }
            #pragma unroll
            for (int nt = 0; nt < 8; nt++) {
                const uint32_t* Bvh = &vh4[nt >> 1][(nt & 1) * 2];
                const uint32_t* Bvl = &vl4[nt >> 1][(nt & 1) * 2];
                mma_bf16(O[nt], pah, Bvh);
                mma_bf16(O[nt], pah, Bvl);
                mma_bf16(O[nt], pal, Bvh);
            }
        }
    }

    // ---- epilogue: normalize and write ctx[b][s][h*64+d] ----
    const float inv0 = 1.f / l0;
    const float inv1 = 1.f / l1;
    float* d0 = g_ctx + ((size_t)bb*SEQ + r0g)*EMBED + hh*HDIM;
    float* d1 = g_ctx + ((size_t)bb*SEQ + r1g)*EMBED + hh*HDIM;
    #pragma unroll
    for (int nt = 0; nt < 8; nt++) {
        const int c = nt*8 + (lane & 3)*2;
        float2 o0; o0.x = O[nt][0]*inv0; o0.y = O[nt][1]*inv0;
        float2 o1; o1.x = O[nt][2]*inv1; o1.y = O[nt][3]*inv1;
        *(float2*)&d0[c] = o0;
        *(float2*)&d1[c] = o1;
    }
}

// ---------------------------------------------------------------------------
extern "C" void kernel_launch(void* const* d_in, const int* in_sizes, int n_in,
                              void* d_out, int out_size)
{
    const float* x     = (const float*)d_in[0];   // [B,S,E]
    const float* w_qkv = (const float*)d_in[1];   // [3E,E]
    const float* b_qkv = (const float*)d_in[2];   // [3E]
    const float* w_out = (const float*)d_in[3];   // [E,E]
    const float* b_out = (const float*)d_in[4];   // [E]
    float* out = (float*)d_out;                   // [B,S,E]

    cudaFuncSetAttribute(attn_tc,
                         cudaFuncAttributeMaxDynamicSharedMemorySize,
                         ATTN_SMEM_BYTES);

    dim3 blk(256);

    // 1. QKV projection + head split (tensor cores, split-bf16)
    gemm_tc<0><<<dim3((3*EMBED)/128, MROWS/128), blk>>>(
        x, w_qkv, b_qkv, nullptr, MROWS, 3*EMBED, EMBED);

    // 2. Causal flash attention (tensor cores, split-bf16) -> g_ctx
    attn_tc<<<dim3(SEQ/128, BATCH*NHEADS), blk, ATTN_SMEM_BYTES>>>();

    // 3. Output projection (tensor cores, split-bf16)
    gemm_tc<1><<<dim3(EMBED/128, MROWS/128), blk>>>(
        nullptr, w_out, b_out, out, MROWS, EMBED, EMBED);
}

// round 5
// speedup vs baseline: 2.6528x; 1.1453x over previous
#include <cuda_runtime.h>
#include <cuda_bf16.h>
#include <cstdint>

#define EMBED   1024
#define NHEADS  16
#define HDIM    64
#define BATCH   2
#define SEQ     2048
#define MROWS   (BATCH*SEQ)   // 4096

#define NEG_INF (-1e30f)

typedef __nv_bfloat16 bf;

// ---------------------------------------------------------------------------
// Scratch (device globals — no allocation allowed). Everything bf16 hi/lo.
// ---------------------------------------------------------------------------
__device__ bf g_Xh[(size_t)MROWS*EMBED],   g_Xl[(size_t)MROWS*EMBED];
__device__ bf g_Wqh[(size_t)3*EMBED*EMBED], g_Wql[(size_t)3*EMBED*EMBED];
__device__ bf g_Woh[(size_t)EMBED*EMBED],  g_Wol[(size_t)EMBED*EMBED];
__device__ bf g_Qh[(size_t)MROWS*EMBED],   g_Ql[(size_t)MROWS*EMBED];
__device__ bf g_Kh[(size_t)MROWS*EMBED],   g_Kl[(size_t)MROWS*EMBED];
__device__ bf g_Vh[(size_t)MROWS*EMBED],   g_Vl[(size_t)MROWS*EMBED];
__device__ bf g_Ch[(size_t)MROWS*EMBED],   g_Cl[(size_t)MROWS*EMBED];

// ---------------------------------------------------------------------------
// PTX helpers
// ---------------------------------------------------------------------------
__device__ __forceinline__ uint32_t saddr(const void* p) {
    return (uint32_t)__cvta_generic_to_shared(p);
}
__device__ __forceinline__ void cpa16(uint32_t dst, const void* src) {
    asm volatile("cp.async.cg.shared.global [%0], [%1], 16;\n" :: "r"(dst), "l"(src));
}
__device__ __forceinline__ void cpa_commit() {
    asm volatile("cp.async.commit_group;\n");
}
template<int N>
__device__ __forceinline__ void cpa_wait() {
    asm volatile("cp.async.wait_group %0;\n" :: "n"(N));
}
__device__ __forceinline__ void ldsm_x4(uint32_t& r0, uint32_t& r1,
                                        uint32_t& r2, uint32_t& r3, uint32_t a) {
    asm volatile("ldmatrix.sync.aligned.m8n8.x4.shared.b16 {%0,%1,%2,%3}, [%4];"
                 : "=r"(r0), "=r"(r1), "=r"(r2), "=r"(r3) : "r"(a));
}
__device__ __forceinline__ void ldsm_x4_t(uint32_t& r0, uint32_t& r1,
                                          uint32_t& r2, uint32_t& r3, uint32_t a) {
    asm volatile("ldmatrix.sync.aligned.m8n8.x4.trans.shared.b16 {%0,%1,%2,%3}, [%4];"
                 : "=r"(r0), "=r"(r1), "=r"(r2), "=r"(r3) : "r"(a));
}
__device__ __forceinline__ void mma_bf16(float* c, const uint32_t* a, const uint32_t* b) {
    asm volatile(
        "mma.sync.aligned.m16n8k16.row.col.f32.bf16.bf16.f32 "
        "{%0,%1,%2,%3}, {%4,%5,%6,%7}, {%8,%9}, {%0,%1,%2,%3};"
        : "+f"(c[0]), "+f"(c[1]), "+f"(c[2]), "+f"(c[3])
        : "r"(a[0]), "r"(a[1]), "r"(a[2]), "r"(a[3]), "r"(b[0]), "r"(b[1]));
}
__device__ __forceinline__ uint32_t pk(bf a, bf b) {
    return (uint32_t)__bfloat16_as_ushort(a) | ((uint32_t)__bfloat16_as_ushort(b) << 16);
}
// split two floats into packed hi bf16x2 and lo bf16x2 (a -> low half)
__device__ __forceinline__ void split_pack(float a, float b, uint32_t& hi, uint32_t& lo) {
    bf ah = __float2bfloat16(a), bh = __float2bfloat16(b);
    hi = pk(ah, bh);
    lo = pk(__float2bfloat16(a - __bfloat162float(ah)),
            __float2bfloat16(b - __bfloat162float(bh)));
}
__device__ __forceinline__ void cvt_store4(float4 f, bf* hp, bf* lp) {
    uint32_t h0, l0, h1, l1;
    split_pack(f.x, f.y, h0, l0);
    split_pack(f.z, f.w, h1, l1);
    uint2 hv; hv.x = h0; hv.y = h1;
    uint2 lv; lv.x = l0; lv.y = l1;
    *(uint2*)hp = hv;
    *(uint2*)lp = lv;
}

// ---------------------------------------------------------------------------
// Input conversion pre-pass: split x, w_qkv, w_out into bf16 hi/lo globals.
// Grid-strided over float4 units: X 1048576, Wq 786432, Wo 262144.
// ---------------------------------------------------------------------------
__global__ __launch_bounds__(256)
void cvt_inputs(const float* __restrict__ x, const float* __restrict__ wq,
                const float* __restrict__ wo)
{
    const int i = blockIdx.x * 256 + threadIdx.x;
    const float* src; bf *dh, *dl; int off;
    if (i < 1048576)            { src = x;  dh = g_Xh;  dl = g_Xl;  off = i; }
    else if (i < 1048576+786432){ src = wq; dh = g_Wqh; dl = g_Wql; off = i - 1048576; }
    else                        { src = wo; dh = g_Woh; dl = g_Wol; off = i - 1835008; }
    float4 f = ((const float4*)src)[off];
    cvt_store4(f, dh + (size_t)off*4, dl + (size_t)off*4);
}

// ---------------------------------------------------------------------------
// Pipelined tensor-core GEMM (split-bf16): out = A @ Bw^T + bias
// Operands pre-split bf16 hi/lo in global. 3-stage cp.async pipeline.
// CTA 128x128, K-step 32, 8 warps (2x4), warp tile 64x32.
// smem stage: Ah,Al,Bh,Bl each [128][40] bf16 (80B rows, conflict-free).
// MODE 0: A=g_X, B=g_Wq, epilogue scatters split Q/K/V.
// MODE 1: A=g_C, B=g_Wo, epilogue fp32 C.
// ---------------------------------------------------------------------------
#define GSTAGE_B  40960          // 4 * 128*40 * 2B
#define GEMM_SMEM (3*GSTAGE_B)   // 122880

template<int MODE>
__global__ __launch_bounds__(256, 1)
void gemm_tc2(const float* __restrict__ bias, float* __restrict__ C,
              int M, int N, int K)
{
    extern __shared__ bf sm[];
    const uint32_t smem0 = saddr(sm);

    const bf* Ahp = (MODE == 0) ? g_Xh : g_Ch;
    const bf* Alp = (MODE == 0) ? g_Xl : g_Cl;
    const bf* Bhp = (MODE == 0) ? g_Wqh : g_Woh;
    const bf* Blp = (MODE == 0) ? g_Wql : g_Wol;

    const int tid  = threadIdx.x;
    const int lane = tid & 31;
    const int warp = tid >> 5;
    const int wm   = warp >> 2;
    const int wn   = warp & 3;
    const int bm   = blockIdx.y * 128;
    const int bn   = blockIdx.x * 128;

    const int lr   = tid >> 1;
    const int half = tid & 1;

    const bf* a0 = Ahp + (size_t)(bm + lr) * K + half*16;
    const bf* a1 = Alp + (size_t)(bm + lr) * K + half*16;
    const bf* b0 = Bhp + (size_t)(bn + lr) * K + half*16;
    const bf* b1 = Blp + (size_t)(bn + lr) * K + half*16;
    const uint32_t dbase = smem0 + lr*80 + half*32;

    const int nsteps = K >> 5;

    auto copy_stage = [&](int k0, int stg) {
        const uint32_t d = dbase + stg * GSTAGE_B;
        cpa16(d,              a0 + k0);  cpa16(d + 16,           a0 + k0 + 8);
        cpa16(d + 10240,      a1 + k0);  cpa16(d + 10240 + 16,   a1 + k0 + 8);
        cpa16(d + 20480,      b0 + k0);  cpa16(d + 20480 + 16,   b0 + k0 + 8);
        cpa16(d + 30720,      b1 + k0);  cpa16(d + 30720 + 16,   b1 + k0 + 8);
    };

    float acc[16][4];
    #pragma unroll
    for (int i = 0; i < 16; i++)
        #pragma unroll
        for (int j = 0; j < 4; j++) acc[i][j] = 0.f;

    const int arow = wm*64 + (lane & 15);
    const int acol = ((lane >> 4) & 1) * 8;
    const int brow = wn*32 + (lane & 7) + ((lane >> 4) & 1) * 8;
    const int bcol = ((lane >> 3) & 1) * 8;
    const uint32_t aoff = (uint32_t)(arow*80 + acol*2);
    const uint32_t boff = (uint32_t)(20480 + brow*80 + bcol*2);

    copy_stage(0, 0);  cpa_commit();
    copy_stage(32, 1); cpa_commit();

    for (int ks = 0; ks < nsteps; ks++) {
        cpa_wait<1>();
        __syncthreads();

        const int nk = ks + 2;
        if (nk < nsteps) copy_stage(nk*32, nk % 3);
        cpa_commit();

        const uint32_t base = smem0 + (ks % 3) * GSTAGE_B;

        #pragma unroll
        for (int kk = 0; kk < 2; kk++) {
            uint32_t ah[4][4], al[4][4], bh[2][4], bl[2][4];
            const uint32_t ab = base + aoff + kk*32;
            const uint32_t bb_ = base + boff + kk*32;
            #pragma unroll
            for (int t = 0; t < 4; t++) {
                ldsm_x4(ah[t][0], ah[t][1], ah[t][2], ah[t][3], ab + t*1280);
                ldsm_x4(al[t][0], al[t][1], al[t][2], al[t][3], ab + 10240 + t*1280);
            }
            #pragma unroll
            for (int p = 0; p < 2; p++) {
                ldsm_x4(bh[p][0], bh[p][1], bh[p][2], bh[p][3], bb_ + p*1280);
                ldsm_x4(bl[p][0], bl[p][1], bl[p][2], bl[p][3], bb_ + 10240 + p*1280);
            }
            #pragma unroll
            for (int t = 0; t < 4; t++) {
                #pragma unroll
                for (int n = 0; n < 4; n++) {
                    float* c = acc[t*4 + n];
                    const uint32_t* Bhf = &bh[n >> 1][(n & 1) * 2];
                    const uint32_t* Blf = &bl[n >> 1][(n & 1) * 2];
                    mma_bf16(c, ah[t], Bhf);
                    mma_bf16(c, ah[t], Blf);
                    mma_bf16(c, al[t], Bhf);
                }
            }
        }
        __syncthreads();
    }

    // epilogue
    #pragma unroll
    for (int t = 0; t < 4; t++) {
        const int r0 = bm + wm*64 + t*16 + (lane >> 2);
        #pragma unroll
        for (int n = 0; n < 4; n++) {
            const int col = bn + wn*32 + n*8 + (lane & 3)*2;
            const float b0v = bias[col], b1v = bias[col + 1];
            const float* c = acc[t*4 + n];
            if (MODE == 0) {
                // scatter split Q/K/V: col in [0,3072)
                const int sel = col >> 10;      // 0=Q 1=K 2=V
                const int e   = col & 1023;
                bf* ph = (sel == 0) ? g_Qh : (sel == 1) ? g_Kh : g_Vh;
                bf* pl = (sel == 0) ? g_Ql : (sel == 1) ? g_Kl : g_Vl;
                const int hh = e >> 6, dd = e & 63;
                #pragma unroll
                for (int rr = 0; rr < 2; rr++) {
                    const int row = r0 + rr*8;
                    const int bbx = row >> 11, ss = row & 2047;
                    const size_t idx = (((size_t)(bbx*NHEADS + hh))*SEQ + ss)*HDIM + dd;
                    uint32_t hi, lo;
                    split_pack(c[rr*2] + b0v, c[rr*2+1] + b1v, hi, lo);
                    *(uint32_t*)&ph[idx] = hi;
                    *(uint32_t*)&pl[idx] = lo;
                }
            } else {
                float2 v0; v0.x = c[0] + b0v; v0.y = c[1] + b1v;
                float2 v1; v1.x = c[2] + b0v; v1.y = c[3] + b1v;
                *(float2*)&C[(size_t)r0       * N + col] = v0;
                *(float2*)&C[(size_t)(r0 + 8) * N + col] = v1;
            }
        }
    }
}

// ---------------------------------------------------------------------------
// Tensor-core flash attention (causal), split-bf16 operands pre-split in
// global. cp.async tile loads (no conversion in loop). q-tile 128, k-tile 64.
// 1/sqrt(d) applied to S post-MMA. Epilogue writes split ctx (g_Ch/g_Cl).
// smem: Qh/Ql[128][72], Kh/Kl/Vh/Vl[64][72]  (144B rows, 16B-aligned)
// ---------------------------------------------------------------------------
#define ATTN_SMEM_BYTES 73728

__global__ __launch_bounds__(256, 1)
void attn_tc()
{
    extern __shared__ bf sb[];
    bf (*Qh)[72] = (bf(*)[72])(sb);
    bf (*Ql)[72] = (bf(*)[72])(sb + 9216);
    bf (*Kh)[72] = (bf(*)[72])(sb + 18432);
    bf (*Kl)[72] = (bf(*)[72])(sb + 23040);
    bf (*Vh)[72] = (bf(*)[72])(sb + 27648);
    bf (*Vl)[72] = (bf(*)[72])(sb + 32256);

    const int qt   = (int)(gridDim.x - 1) - (int)blockIdx.x;   // big tiles first
    const int bhid = blockIdx.y;
    const int bb   = bhid / NHEADS;
    const int hh   = bhid % NHEADS;

    const size_t hb = (size_t)bhid * SEQ * HDIM;

    const int tid  = threadIdx.x;
    const int lane = tid & 31;
    const int w    = tid >> 5;
    const int qbase = qt * 128;

    // ---- load Q tile via cp.async ----
    {
        const int lr = tid >> 1, hf = tid & 1;
        const bf* qh = g_Qh + hb + (size_t)(qbase + lr)*HDIM + hf*32;
        const bf* ql = g_Ql + hb + (size_t)(qbase + lr)*HDIM + hf*32;
        const uint32_t dh = saddr(&Qh[lr][hf*32]);
        const uint32_t dl = saddr(&Ql[lr][hf*32]);
        #pragma unroll
        for (int u = 0; u < 4; u++) {
            cpa16(dh + u*16, qh + u*8);
            cpa16(dl + u*16, ql + u*8);
        }
        cpa_commit();
        cpa_wait<0>();
    }
    __syncthreads();

    // ---- Q fragments (registers, whole kernel) ----
    uint32_t qfh[4][4], qfl[4][4];
    {
        const int arow = w*16 + (lane & 15);
        const int acol = ((lane >> 4) & 1) * 8;
        #pragma unroll
        for (int kc = 0; kc < 4; kc++) {
            ldsm_x4(qfh[kc][0], qfh[kc][1], qfh[kc][2], qfh[kc][3],
                    saddr(&Qh[arow][kc*16 + acol]));
            ldsm_x4(qfl[kc][0], qfl[kc][1], qfl[kc][2], qfl[kc][3],
                    saddr(&Ql[arow][kc*16 + acol]));
        }
    }

    float O[8][4];
    #pragma unroll
    for (int nt = 0; nt < 8; nt++)
        #pragma unroll
        for (int e = 0; e < 4; e++) O[nt][e] = 0.f;

    float m0 = NEG_INF, m1 = NEG_INF, l0 = 0.f, l1 = 0.f;
    const int r0g = qbase + w*16 + (lane >> 2);
    const int r1g = r0g + 8;
    const int wr  = qbase + w*16;

    const int krow = (lane & 7) + ((lane >> 4) & 1) * 8;
    const int kcol = ((lane >> 3) & 1) * 8;
    const int vrow = (lane & 7) + ((lane >> 3) & 1) * 8;
    const int vcol = ((lane >> 4) & 1) * 8;

    const int kr = tid >> 2, q4 = tid & 3;

    const int nktiles = 2*qt + 2;
    for (int kt = 0; kt < nktiles; kt++) {
        const int kbase = kt * 64;
        __syncthreads();   // all warps done reading K/V smem

        // ---- load K and V tiles via cp.async ----
        {
            const size_t srcoff = hb + (size_t)(kbase + kr)*HDIM + q4*16;
            const uint32_t doff = (uint32_t)(kr*144 + q4*32);
            const uint32_t kh = saddr(Kh) + doff, kl = saddr(Kl) + doff;
            const uint32_t vh = saddr(Vh) + doff, vl = saddr(Vl) + doff;
            cpa16(kh, g_Kh + srcoff);  cpa16(kh + 16, g_Kh + srcoff + 8);
            cpa16(kl, g_Kl + srcoff);  cpa16(kl + 16, g_Kl + srcoff + 8);
            cpa16(vh, g_Vh + srcoff);  cpa16(vh + 16, g_Vh + srcoff + 8);
            cpa16(vl, g_Vl + srcoff);  cpa16(vl + 16, g_Vl + srcoff + 8);
            cpa_commit();
            cpa_wait<0>();
        }
        __syncthreads();

        if (wr + 15 < kbase) continue;   // warp fully masked for this tile

        // ---- S = Q K^T ----
        float s[8][4];
        #pragma unroll
        for (int nt = 0; nt < 8; nt++)
            #pragma unroll
            for (int e = 0; e < 4; e++) s[nt][e] = 0.f;

        #pragma unroll
        for (int kc = 0; kc < 4; kc++) {
            uint32_t kh4[4][4], kl4[4][4];
            #pragma unroll
            for (int p = 0; p < 4; p++) {
                ldsm_x4(kh4[p][0], kh4[p][1], kh4[p][2], kh4[p][3],
                        saddr(&Kh[p*16 + krow][kc*16 + kcol]));
                ldsm_x4(kl4[p][0], kl4[p][1], kl4[p][2], kl4[p][3],
                        saddr(&Kl[p*16 + krow][kc*16 + kcol]));
            }
            #pragma unroll
            for (int nt = 0; nt < 8; nt++) {
                const uint32_t* Bhf = &kh4[nt >> 1][(nt & 1) * 2];
                const uint32_t* Blf = &kl4[nt >> 1][(nt & 1) * 2];
                mma_bf16(s[nt], qfh[kc], Bhf);
                mma_bf16(s[nt], qfh[kc], Blf);
                mma_bf16(s[nt], qfl[kc], Bhf);
            }
        }

        // scale + causal mask
        #pragma unroll
        for (int nt = 0; nt < 8; nt++)
            #pragma unroll
            for (int e = 0; e < 4; e++) s[nt][e] *= 0.125f;

        if (kbase + 63 > wr) {
            #pragma unroll
            for (int nt = 0; nt < 8; nt++) {
                const int c0 = kbase + nt*8 + ((lane & 3) << 1);
                if (c0     > r0g) s[nt][0] = NEG_INF;
                if (c0 + 1 > r0g) s[nt][1] = NEG_INF;
                if (c0     > r1g) s[nt][2] = NEG_INF;
                if (c0 + 1 > r1g) s[nt][3] = NEG_INF;
            }
        }

        // ---- online softmax ----
        float mx0 = NEG_INF, mx1 = NEG_INF;
        #pragma unroll
        for (int nt = 0; nt < 8; nt++) {
            mx0 = fmaxf(mx0, fmaxf(s[nt][0], s[nt][1]));
            mx1 = fmaxf(mx1, fmaxf(s[nt][2], s[nt][3]));
        }
        mx0 = fmaxf(mx0, __shfl_xor_sync(0xffffffffu, mx0, 1));
        mx0 = fmaxf(mx0, __shfl_xor_sync(0xffffffffu, mx0, 2));
        mx1 = fmaxf(mx1, __shfl_xor_sync(0xffffffffu, mx1, 1));
        mx1 = fmaxf(mx1, __shfl_xor_sync(0xffffffffu, mx1, 2));

        const float nm0 = fmaxf(m0, mx0);
        const float nm1 = fmaxf(m1, mx1);
        const float f0 = __expf(m0 - nm0);
        const float f1 = __expf(m1 - nm1);

        float ps0 = 0.f, ps1 = 0.f;
        #pragma unroll
        for (int nt = 0; nt < 8; nt++) {
            s[nt][0] = __expf(s[nt][0] - nm0);
            s[nt][1] = __expf(s[nt][1] - nm0);
            s[nt][2] = __expf(s[nt][2] - nm1);
            s[nt][3] = __expf(s[nt][3] - nm1);
            ps0 += s[nt][0] + s[nt][1];
            ps1 += s[nt][2] + s[nt][3];
        }
        ps0 += __shfl_xor_sync(0xffffffffu, ps0, 1);
        ps0 += __shfl_xor_sync(0xffffffffu, ps0, 2);
        ps1 += __shfl_xor_sync(0xffffffffu, ps1, 1);
        ps1 += __shfl_xor_sync(0xffffffffu, ps1, 2);

        l0 = l0 * f0 + ps0;  m0 = nm0;
        l1 = l1 * f1 + ps1;  m1 = nm1;

        #pragma unroll
        for (int nt = 0; nt < 8; nt++) {
            O[nt][0] *= f0; O[nt][1] *= f0;
            O[nt][2] *= f1; O[nt][3] *= f1;
        }

        // ---- O += P V ----
        #pragma unroll
        for (int kc = 0; kc < 4; kc++) {
            uint32_t pah[4], pal[4];
            split_pack(s[2*kc  ][0], s[2*kc  ][1], pah[0], pal[0]);
            split_pack(s[2*kc  ][2], s[2*kc  ][3], pah[1], pal[1]);
            split_pack(s[2*kc+1][0], s[2*kc+1][1], pah[2], pal[2]);
            split_pack(s[2*kc+1][2], s[2*kc+1][3], pah[3], pal[3]);

            uint32_t vh4[4][4], vl4[4][4];
            #pragma unroll
            for (int p = 0; p < 4; p++) {
                ldsm_x4_t(vh4[p][0], vh4[p][1], vh4[p][2], vh4[p][3],
                          saddr(&Vh[kc*16 + vrow][p*16 + vcol]));
                ldsm_x4_t(vl4[p][0], vl4[p][1], vl4[p][2], vl4[p][3],
                          saddr(&Vl[kc*16 + vrow][p*16 + vcol]));
            }
            #pragma unroll
            for (int nt = 0; nt < 8; nt++) {
                const uint32_t* Bvh = &vh4[nt >> 1][(nt & 1) * 2];
                const uint32_t* Bvl = &vl4[nt >> 1][(nt & 1) * 2];
                mma_bf16(O[nt], pah, Bvh);
                mma_bf16(O[nt], pah, Bvl);
                mma_bf16(O[nt], pal, Bvh);
            }
        }
    }

    // ---- epilogue: normalize, split, write ctx hi/lo ----
    const float inv0 = 1.f / l0;
    const float inv1 = 1.f / l1;
    const size_t i0 = ((size_t)bb*SEQ + r0g)*EMBED + hh*HDIM;
    const size_t i1 = ((size_t)bb*SEQ + r1g)*EMBED + hh*HDIM;
    #pragma unroll
    for (int nt = 0; nt < 8; nt++) {
        const int c = nt*8 + (lane & 3)*2;
        uint32_t hi, lo;
        split_pack(O[nt][0]*inv0, O[nt][1]*inv0, hi, lo);
        *(uint32_t*)&g_Ch[i0 + c] = hi;
        *(uint32_t*)&g_Cl[i0 + c] = lo;
        split_pack(O[nt][2]*inv1, O[nt][3]*inv1, hi, lo);
        *(uint32_t*)&g_Ch[i1 + c] = hi;
        *(uint32_t*)&g_Cl[i1 + c] = lo;
    }
}

// ---------------------------------------------------------------------------
extern "C" void kernel_launch(void* const* d_in, const int* in_sizes, int n_in,
                              void* d_out, int out_size)
{
    const float* x     = (const float*)d_in[0];   // [B,S,E]
    const float* w_qkv = (const float*)d_in[1];   // [3E,E]
    const float* b_qkv = (const float*)d_in[2];   // [3E]
    const float* w_out = (const float*)d_in[3];   // [E,E]
    const float* b_out = (const float*)d_in[4];   // [E]
    float* out = (float*)d_out;                   // [B,S,E]

    cudaFuncSetAttribute(attn_tc, cudaFuncAttributeMaxDynamicSharedMemorySize,
                         ATTN_SMEM_BYTES);
    cudaFuncSetAttribute(gemm_tc2<0>, cudaFuncAttributeMaxDynamicSharedMemorySize,
                         GEMM_SMEM);
    cudaFuncSetAttribute(gemm_tc2<1>, cudaFuncAttributeMaxDynamicSharedMemorySize,
                         GEMM_SMEM);

    dim3 blk(256);

    // 0. split inputs/weights to bf16 hi/lo
    cvt_inputs<<<8192, blk>>>(x, w_qkv, w_out);

    // 1. QKV projection + head split (pipelined TC gemm, split-bf16)
    gemm_tc2<0><<<dim3((3*EMBED)/128, MROWS/128), blk, GEMM_SMEM>>>(
        b_qkv, nullptr, MROWS, 3*EMBED, EMBED);

    // 2. Causal flash attention (TC, split-bf16) -> split ctx
    attn_tc<<<dim3(SEQ/128, BATCH*NHEADS), blk, ATTN_SMEM_BYTES>>>();

    // 3. Output projection (pipelined TC gemm, split-bf16)
    gemm_tc2<1><<<dim3(EMBED/128, MROWS/128), blk, GEMM_SMEM>>>(
        b_out, out, MROWS, EMBED, EMBED);
}